// round 10
// baseline (speedup 1.0000x reference)
#include <cuda_runtime.h>
#include <cstdint>

#define B_  64
#define HW_ 4096
#define C_  128      // N
#define P_  64       // K
#define NCHUNK 32
#define TILE_M 128

#define PITCH_A 68    // s-tile smem pitch (floats)
#define PITCH_B 136   // k-tile smem pitch (floats)
#define SMEM_FLOATS (128 * PITCH_A + P_ * PITCH_B)   // 17408 floats = 69632 B

// ---------------- scratch ----------------
__device__ float g_zsum[(size_t)B_ * NCHUNK * C_];
__device__ float g_z2[(size_t)B_ * NCHUNK];

// ---------------- helpers ----------------
__device__ __forceinline__ uint32_t tf32_rna(float a) {
    uint32_t r;
    asm("cvt.rna.tf32.f32 %0, %1;" : "=r"(r) : "f"(a));
    return r;
}

__device__ __forceinline__ void mma_tf32(float* d, const uint32_t* a,
                                         uint32_t b0, uint32_t b1) {
    asm volatile(
        "mma.sync.aligned.m16n8k8.row.col.f32.tf32.tf32.f32 "
        "{%0,%1,%2,%3}, {%4,%5,%6,%7}, {%8,%9}, {%0,%1,%2,%3};"
        : "+f"(d[0]), "+f"(d[1]), "+f"(d[2]), "+f"(d[3])
        : "r"(a[0]), "r"(a[1]), "r"(a[2]), "r"(a[3]), "r"(b0), "r"(b1));
}

// ---------------- fused kernel: z-reduce + tf32 GEMM ----------------
// grid 2048, block 256 (8 warps), target occupancy 3.
__global__ __launch_bounds__(256, 3)
void fused_kernel(const float* __restrict__ z, const float* __restrict__ s,
                  const float* __restrict__ kk, float* __restrict__ out) {
    extern __shared__ float sm[];
    float* sA = sm;                        // [128][PITCH_A] s tile
    float* sB = sm + 128 * PITCH_A;        // [P_][PITCH_B]  k

    __shared__ float4 sred[256];
    __shared__ float  sz2[8];

    const int tid  = threadIdx.x;
    const int wid  = tid >> 5;
    const int lane = tid & 31;
    const int bx   = blockIdx.x;
    const size_t m0 = (size_t)bx * TILE_M;

    // ---- stage s tile: 128 rows x 64 floats ----
    #pragma unroll
    for (int i = 0; i < 8; ++i) {
        const int idx = tid + i * 256;
        const int r = idx >> 4, q = idx & 15;
        float4 v = ((const float4*)(s + (m0 + r) * P_))[q];
        *(float4*)(sA + r * PITCH_A + q * 4) = v;
    }
    // ---- stage k: 64 rows x 128 floats ----
    #pragma unroll
    for (int i = 0; i < 8; ++i) {
        const int idx = tid + i * 256;
        const int p = idx >> 5, q = idx & 31;
        float4 v = ((const float4*)(kk + (size_t)p * C_))[q];
        *(float4*)(sB + p * PITCH_B + q * 4) = v;
    }

    // ---- z reduction phase ----
    {
        const int b     = bx >> 5;
        const int chunk = bx & 31;
        const float4* base =
            (const float4*)(z + ((size_t)b * HW_ + (size_t)chunk * 128) * C_);
        const int cq = tid & 31;
        const int rg = tid >> 5;

        float4 acc = make_float4(0.f, 0.f, 0.f, 0.f);
        float z2 = 0.f;
        #pragma unroll
        for (int j = 0; j < 16; ++j) {
            float4 v = base[(size_t)(rg + 8 * j) * (C_ / 4) + cq];
            acc.x += v.x; acc.y += v.y; acc.z += v.z; acc.w += v.w;
            z2 += v.x * v.x + v.y * v.y + v.z * v.z + v.w * v.w;
        }
        #pragma unroll
        for (int off = 16; off > 0; off >>= 1)
            z2 += __shfl_down_sync(0xffffffffu, z2, off);
        sred[tid] = acc;
        if (lane == 0) sz2[rg] = z2;
        __syncthreads();

        if (rg == 0) {
            float4 t = sred[cq];
            #pragma unroll
            for (int g = 1; g < 8; ++g) {
                float4 v = sred[g * 32 + cq];
                t.x += v.x; t.y += v.y; t.z += v.z; t.w += v.w;
            }
            ((float4*)(g_zsum + ((size_t)b * NCHUNK + chunk) * C_))[cq] = t;
            if (cq == 0) {
                float tt = 0.f;
                #pragma unroll
                for (int g = 0; g < 8; ++g) tt += sz2[g];
                g_z2[(size_t)b * NCHUNK + chunk] = tt;
            }
        }
    }
    __syncthreads();   // staging + reduction done

    // ---- MMA phase: warp grid 4(M) x 2(N); warp tile 32x64 ----
    const int warpM = wid & 3;
    const int warpN = wid >> 2;
    const int lq = lane >> 2;   // 0..7
    const int lr = lane & 3;    // 0..3

    float acc[2][8][4];
    #pragma unroll
    for (int mi = 0; mi < 2; ++mi)
        #pragma unroll
        for (int ni = 0; ni < 8; ++ni)
            #pragma unroll
            for (int j = 0; j < 4; ++j) acc[mi][ni][j] = 0.f;

    #pragma unroll
    for (int k0 = 0; k0 < P_; k0 += 8) {
        uint32_t ah[2][4], al[2][4];
        #pragma unroll
        for (int mi = 0; mi < 2; ++mi) {
            const int r = warpM * 32 + mi * 16 + lq;
            const float* base = sA + r * PITCH_A + k0 + lr;
            const float a0 = base[0];
            const float a1 = base[8 * PITCH_A];
            const float a2 = base[4];
            const float a3 = base[8 * PITCH_A + 4];
            ah[mi][0] = tf32_rna(a0); al[mi][0] = tf32_rna(a0 - __uint_as_float(ah[mi][0]));
            ah[mi][1] = tf32_rna(a1); al[mi][1] = tf32_rna(a1 - __uint_as_float(ah[mi][1]));
            ah[mi][2] = tf32_rna(a2); al[mi][2] = tf32_rna(a2 - __uint_as_float(ah[mi][2]));
            ah[mi][3] = tf32_rna(a3); al[mi][3] = tf32_rna(a3 - __uint_as_float(ah[mi][3]));
        }
        #pragma unroll
        for (int ni = 0; ni < 8; ++ni) {
            const int c = warpN * 64 + ni * 8 + lq;
            const float b0 = sB[(k0 + lr) * PITCH_B + c];
            const float b1 = sB[(k0 + lr + 4) * PITCH_B + c];
            const uint32_t bh0 = tf32_rna(b0);
            const uint32_t bh1 = tf32_rna(b1);
            const uint32_t bl0 = tf32_rna(b0 - __uint_as_float(bh0));
            const uint32_t bl1 = tf32_rna(b1 - __uint_as_float(bh1));
            #pragma unroll
            for (int mi = 0; mi < 2; ++mi) {
                mma_tf32(acc[mi][ni], ah[mi], bh0, bh1);  // hi*hi
                mma_tf32(acc[mi][ni], ah[mi], bl0, bl1);  // hi*lo
                mma_tf32(acc[mi][ni], al[mi], bh0, bh1);  // lo*hi
            }
        }
    }

    // ---- epilogue ----
    #pragma unroll
    for (int mi = 0; mi < 2; ++mi) {
        const size_t row = m0 + warpM * 32 + mi * 16 + lq;
        #pragma unroll
        for (int ni = 0; ni < 8; ++ni) {
            const int col = warpN * 64 + ni * 8 + 2 * lr;
            *(float2*)(out + row * C_ + col) =
                make_float2(acc[mi][ni][0], acc[mi][ni][1]);
            *(float2*)(out + (row + 8) * C_ + col) =
                make_float2(acc[mi][ni][2], acc[mi][ni][3]);
        }
    }
}

// ---------------- Kernel 2: distance (parallelized) ----------------
__global__ __launch_bounds__(256)
void dist_kernel(const float* __restrict__ kk, float* __restrict__ dist) {
    const int b = blockIdx.x;
    const int tid = threadIdx.x;
    __shared__ float part[2][C_];
    __shared__ float zs[C_];
    __shared__ float z2s;

    {
        const int c    = tid & 127;
        const int half = tid >> 7;
        const float* base = g_zsum + ((size_t)b * NCHUNK + half * 16) * C_ + c;
        float a = 0.f;
        #pragma unroll
        for (int ch = 0; ch < 16; ++ch) a += base[(size_t)ch * C_];
        part[half][c] = a;
    }
    if (tid < 32) {
        float t = g_z2[(size_t)b * NCHUNK + tid];
        #pragma unroll
        for (int off = 16; off > 0; off >>= 1)
            t += __shfl_down_sync(0xffffffffu, t, off);
        if (tid == 0) z2s = t;
    }
    __syncthreads();
    if (tid < C_) zs[tid] = part[0][tid] + part[1][tid];
    __syncthreads();

    {
        const int p   = tid >> 2;
        const int sub = tid & 3;
        const float* kp = kk + (size_t)p * C_ + sub * 32;
        const float* zp = zs + sub * 32;
        float dot = 0.f, k2 = 0.f;
        #pragma unroll
        for (int c = 0; c < 32; ++c) {
            const float kv = kp[c];
            dot += zp[c] * kv;
            k2  += kv * kv;
        }
        dot += __shfl_xor_sync(0xffffffffu, dot, 1);
        k2  += __shfl_xor_sync(0xffffffffu, k2, 1);
        dot += __shfl_xor_sync(0xffffffffu, dot, 2);
        k2  += __shfl_xor_sync(0xffffffffu, k2, 2);
        if (sub == 0)
            dist[(size_t)b * P_ + p] = z2s - 2.f * dot + (float)HW_ * k2;
    }
}

// ---------------- launch ----------------
extern "C" void kernel_launch(void* const* d_in, const int* in_sizes, int n_in,
                              void* d_out, int out_size) {
    const float* z = (const float*)d_in[0];
    const float* s = (const float*)d_in[1];
    const float* k = (const float*)d_in[2];
    float* out  = (float*)d_out;
    float* dist = out + (size_t)in_sizes[0];

    static bool attr_set = false;
    if (!attr_set) {
        cudaFuncSetAttribute(fused_kernel,
                             cudaFuncAttributeMaxDynamicSharedMemorySize,
                             SMEM_FLOATS * (int)sizeof(float));
        attr_set = true;
    }

    fused_kernel<<<(B_ * HW_) / TILE_M, 256, SMEM_FLOATS * sizeof(float)>>>(
        z, s, k, out);
    dist_kernel<<<B_, 256>>>(k, dist);
}

// round 11
// speedup vs baseline: 1.2477x; 1.2477x over previous
#include <cuda_runtime.h>
#include <cstdint>

#define B_  64
#define HW_ 4096
#define C_  128      // N
#define P_  64       // K
#define NCHUNK 32
#define TILE_M 128

#define PITCH_A 68    // s-tile smem pitch (floats)
#define PITCH_B 136   // k-tile smem pitch (floats)
#define SMEM_FLOATS (128 * PITCH_A + P_ * PITCH_B)   // 69632 B

// ---------------- scratch ----------------
__device__ float g_zsum[(size_t)B_ * NCHUNK * C_];
__device__ float g_z2[(size_t)B_ * NCHUNK];

// ---------------- helpers ----------------
__device__ __forceinline__ uint32_t tf32_rna(float a) {
    uint32_t r;
    asm("cvt.rna.tf32.f32 %0, %1;" : "=r"(r) : "f"(a));
    return r;
}

__device__ __forceinline__ void mma_tf32(float* d, const uint32_t* a,
                                         uint32_t b0, uint32_t b1) {
    asm volatile(
        "mma.sync.aligned.m16n8k8.row.col.f32.tf32.tf32.f32 "
        "{%0,%1,%2,%3}, {%4,%5,%6,%7}, {%8,%9}, {%0,%1,%2,%3};"
        : "+f"(d[0]), "+f"(d[1]), "+f"(d[2]), "+f"(d[3])
        : "r"(a[0]), "r"(a[1]), "r"(a[2]), "r"(a[3]), "r"(b0), "r"(b1));
}

// ---------------- Kernel A1: z reduction ----------------
__global__ __launch_bounds__(256)
void zreduce_kernel(const float* __restrict__ z) {
    const int chunk = blockIdx.x;
    const int b     = blockIdx.y;
    const int tid   = threadIdx.x;
    const float4* base =
        (const float4*)(z + ((size_t)b * HW_ + (size_t)chunk * 128) * C_);

    const int cq = tid & 31;
    const int rg = tid >> 5;

    __shared__ float4 sred[256];
    __shared__ float  sz2[8];

    float4 acc = make_float4(0.f, 0.f, 0.f, 0.f);
    float z2 = 0.f;
    #pragma unroll
    for (int j = 0; j < 16; ++j) {
        float4 v = base[(size_t)(rg + 8 * j) * (C_ / 4) + cq];
        acc.x += v.x; acc.y += v.y; acc.z += v.z; acc.w += v.w;
        z2 += v.x * v.x + v.y * v.y + v.z * v.z + v.w * v.w;
    }
    #pragma unroll
    for (int off = 16; off > 0; off >>= 1)
        z2 += __shfl_down_sync(0xffffffffu, z2, off);
    sred[tid] = acc;
    if (cq == 0) sz2[rg] = z2;
    __syncthreads();

    if (rg == 0) {
        float4 t = sred[cq];
        #pragma unroll
        for (int g = 1; g < 8; ++g) {
            float4 v = sred[g * 32 + cq];
            t.x += v.x; t.y += v.y; t.z += v.z; t.w += v.w;
        }
        ((float4*)(g_zsum + ((size_t)b * NCHUNK + chunk) * C_))[cq] = t;
        if (cq == 0) {
            float tt = 0.f;
            #pragma unroll
            for (int g = 0; g < 8; ++g) tt += sz2[g];
            g_z2[(size_t)b * NCHUNK + chunk] = tt;
        }
    }
}

// ---------------- Kernel A2: distance ----------------
__global__ __launch_bounds__(256)
void dist_kernel(const float* __restrict__ kk, float* __restrict__ dist) {
    const int b = blockIdx.x;
    const int tid = threadIdx.x;
    __shared__ float part[2][C_];
    __shared__ float zs[C_];
    __shared__ float z2s;

    {
        const int c    = tid & 127;
        const int half = tid >> 7;
        const float* base = g_zsum + ((size_t)b * NCHUNK + half * 16) * C_ + c;
        float a = 0.f;
        #pragma unroll
        for (int ch = 0; ch < 16; ++ch) a += base[(size_t)ch * C_];
        part[half][c] = a;
    }
    if (tid < 32) {
        float t = g_z2[(size_t)b * NCHUNK + tid];
        #pragma unroll
        for (int off = 16; off > 0; off >>= 1)
            t += __shfl_down_sync(0xffffffffu, t, off);
        if (tid == 0) z2s = t;
    }
    __syncthreads();
    if (tid < C_) zs[tid] = part[0][tid] + part[1][tid];
    __syncthreads();

    {
        const int p   = tid >> 2;
        const int sub = tid & 3;
        const float* kp = kk + (size_t)p * C_ + sub * 32;
        const float* zp = zs + sub * 32;
        float dot = 0.f, k2 = 0.f;
        #pragma unroll
        for (int c = 0; c < 32; ++c) {
            const float kv = kp[c];
            dot += zp[c] * kv;
            k2  += kv * kv;
        }
        dot += __shfl_xor_sync(0xffffffffu, dot, 1);
        k2  += __shfl_xor_sync(0xffffffffu, k2, 1);
        dot += __shfl_xor_sync(0xffffffffu, dot, 2);
        k2  += __shfl_xor_sync(0xffffffffu, k2, 2);
        if (sub == 0)
            dist[(size_t)b * P_ + p] = z2s - 2.f * dot + (float)HW_ * k2;
    }
}

// ---------------- Kernel B: tf32 GEMM (R8 core, z-free) ----------------
__global__ __launch_bounds__(256, 2)
void gemm_kernel(const float* __restrict__ s, const float* __restrict__ kk,
                 float* __restrict__ out) {
    extern __shared__ float sm[];
    float* sA = sm;                        // [128][PITCH_A]
    float* sB = sm + 128 * PITCH_A;        // [P_][PITCH_B]

    const int tid  = threadIdx.x;
    const int wid  = tid >> 5;
    const int lane = tid & 31;
    const size_t m0 = (size_t)blockIdx.x * TILE_M;

    #pragma unroll
    for (int i = 0; i < 8; ++i) {
        const int idx = tid + i * 256;
        const int r = idx >> 4, q = idx & 15;
        float4 v = ((const float4*)(s + (m0 + r) * P_))[q];
        *(float4*)(sA + r * PITCH_A + q * 4) = v;
    }
    #pragma unroll
    for (int i = 0; i < 8; ++i) {
        const int idx = tid + i * 256;
        const int p = idx >> 5, q = idx & 31;
        float4 v = ((const float4*)(kk + (size_t)p * C_))[q];
        *(float4*)(sB + p * PITCH_B + q * 4) = v;
    }
    __syncthreads();

    const int warpM = wid & 3;
    const int warpN = wid >> 2;
    const int lq = lane >> 2;
    const int lr = lane & 3;

    float acc[2][8][4];
    #pragma unroll
    for (int mi = 0; mi < 2; ++mi)
        #pragma unroll
        for (int ni = 0; ni < 8; ++ni)
            #pragma unroll
            for (int j = 0; j < 4; ++j) acc[mi][ni][j] = 0.f;

    #pragma unroll
    for (int k0 = 0; k0 < P_; k0 += 8) {
        uint32_t ah[2][4], al[2][4];
        #pragma unroll
        for (int mi = 0; mi < 2; ++mi) {
            const int r = warpM * 32 + mi * 16 + lq;
            const float* base = sA + r * PITCH_A + k0 + lr;
            const float a0 = base[0];
            const float a1 = base[8 * PITCH_A];
            const float a2 = base[4];
            const float a3 = base[8 * PITCH_A + 4];
            ah[mi][0] = tf32_rna(a0); al[mi][0] = tf32_rna(a0 - __uint_as_float(ah[mi][0]));
            ah[mi][1] = tf32_rna(a1); al[mi][1] = tf32_rna(a1 - __uint_as_float(ah[mi][1]));
            ah[mi][2] = tf32_rna(a2); al[mi][2] = tf32_rna(a2 - __uint_as_float(ah[mi][2]));
            ah[mi][3] = tf32_rna(a3); al[mi][3] = tf32_rna(a3 - __uint_as_float(ah[mi][3]));
        }
        #pragma unroll
        for (int ni = 0; ni < 8; ++ni) {
            const int c = warpN * 64 + ni * 8 + lq;
            const float b0 = sB[(k0 + lr) * PITCH_B + c];
            const float b1 = sB[(k0 + lr + 4) * PITCH_B + c];
            const uint32_t bh0 = tf32_rna(b0);
            const uint32_t bh1 = tf32_rna(b1);
            const uint32_t bl0 = tf32_rna(b0 - __uint_as_float(bh0));
            const uint32_t bl1 = tf32_rna(b1 - __uint_as_float(bh1));
            #pragma unroll
            for (int mi = 0; mi < 2; ++mi) {
                mma_tf32(acc[mi][ni], ah[mi], bh0, bh1);
                mma_tf32(acc[mi][ni], ah[mi], bl0, bl1);
                mma_tf32(acc[mi][ni], al[mi], bh0, bh1);
            }
        }
    }

    #pragma unroll
    for (int mi = 0; mi < 2; ++mi) {
        const size_t row = m0 + warpM * 32 + mi * 16 + lq;
        #pragma unroll
        for (int ni = 0; ni < 8; ++ni) {
            const int col = warpN * 64 + ni * 8 + 2 * lr;
            *(float2*)(out + row * C_ + col) =
                make_float2(acc[mi][ni][0], acc[mi][ni][1]);
            *(float2*)(out + (row + 8) * C_ + col) =
                make_float2(acc[mi][ni][2], acc[mi][ni][3]);
        }
    }
}

// ---------------- launch: fork-join two pipelines ----------------
extern "C" void kernel_launch(void* const* d_in, const int* in_sizes, int n_in,
                              void* d_out, int out_size) {
    const float* z = (const float*)d_in[0];
    const float* s = (const float*)d_in[1];
    const float* k = (const float*)d_in[2];
    float* out  = (float*)d_out;
    float* dist = out + (size_t)in_sizes[0];

    static cudaStream_t s2 = nullptr;
    static cudaEvent_t e_fork, e_join;
    if (!s2) {
        cudaStreamCreateWithFlags(&s2, cudaStreamNonBlocking);
        cudaEventCreateWithFlags(&e_fork, cudaEventDisableTiming);
        cudaEventCreateWithFlags(&e_join, cudaEventDisableTiming);
        cudaFuncSetAttribute(gemm_kernel,
                             cudaFuncAttributeMaxDynamicSharedMemorySize,
                             SMEM_FLOATS * (int)sizeof(float));
    }

    // fork: branch A (zreduce -> dist) on s2, branch B (gemm) on main stream
    cudaEventRecord(e_fork, 0);
    cudaStreamWaitEvent(s2, e_fork, 0);

    zreduce_kernel<<<dim3(NCHUNK, B_), 256, 0, s2>>>(z);
    dist_kernel<<<B_, 256, 0, s2>>>(k, dist);
    cudaEventRecord(e_join, s2);

    gemm_kernel<<<(B_ * HW_) / TILE_M, 256, SMEM_FLOATS * sizeof(float)>>>(
        s, k, out);

    // join
    cudaStreamWaitEvent(0, e_join, 0);
}

// round 12
// speedup vs baseline: 1.3302x; 1.0661x over previous
#include <cuda_runtime.h>
#include <cstdint>

#define B_  64
#define HW_ 4096
#define C_  128      // N
#define P_  64       // K
#define NCHUNK 32
#define TILE_M 128

// smem tiles (bf16 hi/lo), pitch 72 bf16 (=36 words) for conflict-free frags
#define PITCH_W 36                       // words per row
#define A_TILE_W (128 * PITCH_W)         // words per A tile
#define B_TILE_W (128 * PITCH_W)         // words per B tile (n rows x k)
#define SMEM_WORDS (2 * A_TILE_W + 2 * B_TILE_W)   // 73728 bytes

// ---------------- scratch ----------------
__device__ float g_zsum[(size_t)B_ * NCHUNK * C_];
__device__ float g_z2[(size_t)B_ * NCHUNK];

// ---------------- helpers ----------------
// pack bf16(a) (low) and bf16(b) (high) into one word
__device__ __forceinline__ uint32_t bf16x2_rn(float a, float b) {
    uint32_t r;
    asm("cvt.rn.bf16x2.f32 %0, %1, %2;" : "=r"(r) : "f"(b), "f"(a));
    return r;
}
// split 2 floats into hi-pair and lo-pair words (bf16x2 each)
__device__ __forceinline__ void split2(float a, float b, uint32_t& h, uint32_t& l) {
    h = bf16x2_rn(a, b);
    const float fh0 = __uint_as_float(h << 16);
    const float fh1 = __uint_as_float(h & 0xFFFF0000u);
    l = bf16x2_rn(a - fh0, b - fh1);
}

__device__ __forceinline__ void mma_bf16(float* d, const uint32_t* a,
                                         uint32_t b0, uint32_t b1) {
    asm volatile(
        "mma.sync.aligned.m16n8k16.row.col.f32.bf16.bf16.f32 "
        "{%0,%1,%2,%3}, {%4,%5,%6,%7}, {%8,%9}, {%0,%1,%2,%3};"
        : "+f"(d[0]), "+f"(d[1]), "+f"(d[2]), "+f"(d[3])
        : "r"(a[0]), "r"(a[1]), "r"(a[2]), "r"(a[3]), "r"(b0), "r"(b1));
}

// ---------------- fused kernel: z-reduce + 3xBF16 GEMM ----------------
// grid 2048, block 256 (8 warps), occ 2.
__global__ __launch_bounds__(256, 2)
void fused_kernel(const float* __restrict__ z, const float* __restrict__ s,
                  const float* __restrict__ kk, float* __restrict__ out) {
    extern __shared__ uint32_t sm[];
    uint32_t* sAh = sm;                    // [128 rows][36 w]  A hi
    uint32_t* sAl = sAh + A_TILE_W;        // A lo
    uint32_t* sBh = sAl + A_TILE_W;        // [128 n][36 w]     B hi
    uint32_t* sBl = sBh + B_TILE_W;        // B lo

    __shared__ float4 sred[256];
    __shared__ float  sz2[8];

    const int tid  = threadIdx.x;
    const int wid  = tid >> 5;
    const int lane = tid & 31;
    const int bx   = blockIdx.x;
    const size_t m0 = (size_t)bx * TILE_M;

    // ---- stage s tile (A): [m][k] k-contiguous -> pairs along k are easy ----
    #pragma unroll
    for (int i = 0; i < 8; ++i) {
        const int idx = tid + i * 256;          // 0..2047 float4
        const int r = idx >> 4, q = idx & 15;   // q: float4 index along k
        float4 v = ((const float4*)(s + (m0 + r) * P_))[q];
        uint32_t h0, l0, h1, l1;
        split2(v.x, v.y, h0, l0);
        split2(v.z, v.w, h1, l1);
        uint32_t* ph = sAh + r * PITCH_W + q * 2;
        uint32_t* pl = sAl + r * PITCH_W + q * 2;
        ph[0] = h0; ph[1] = h1;
        pl[0] = l0; pl[1] = l1;
    }
    // ---- stage k (B): need [n][k] pairs along k -> read two adjacent k rows ----
    #pragma unroll
    for (int i = 0; i < 4; ++i) {
        const int idx = tid + i * 256;          // 0..1023: (kpair, cq)
        const int kp = idx >> 5;                // k pair 0..31 (k = 2kp, 2kp+1)
        const int cq = idx & 31;                // float4 along c
        float4 v0 = ((const float4*)(kk + (size_t)(2 * kp)     * C_))[cq];
        float4 v1 = ((const float4*)(kk + (size_t)(2 * kp + 1) * C_))[cq];
        const int n0 = cq * 4;
        uint32_t h, l;
        split2(v0.x, v1.x, h, l);
        sBh[(n0 + 0) * PITCH_W + kp] = h; sBl[(n0 + 0) * PITCH_W + kp] = l;
        split2(v0.y, v1.y, h, l);
        sBh[(n0 + 1) * PITCH_W + kp] = h; sBl[(n0 + 1) * PITCH_W + kp] = l;
        split2(v0.z, v1.z, h, l);
        sBh[(n0 + 2) * PITCH_W + kp] = h; sBl[(n0 + 2) * PITCH_W + kp] = l;
        split2(v0.w, v1.w, h, l);
        sBh[(n0 + 3) * PITCH_W + kp] = h; sBl[(n0 + 3) * PITCH_W + kp] = l;
    }

    // ---- z reduction phase (proven R8/R11 code) ----
    {
        const int b     = bx >> 5;
        const int chunk = bx & 31;
        const float4* base =
            (const float4*)(z + ((size_t)b * HW_ + (size_t)chunk * 128) * C_);
        const int cq = tid & 31;
        const int rg = tid >> 5;

        float4 acc = make_float4(0.f, 0.f, 0.f, 0.f);
        float z2 = 0.f;
        #pragma unroll
        for (int j = 0; j < 16; ++j) {
            float4 v = base[(size_t)(rg + 8 * j) * (C_ / 4) + cq];
            acc.x += v.x; acc.y += v.y; acc.z += v.z; acc.w += v.w;
            z2 += v.x * v.x + v.y * v.y + v.z * v.z + v.w * v.w;
        }
        #pragma unroll
        for (int off = 16; off > 0; off >>= 1)
            z2 += __shfl_down_sync(0xffffffffu, z2, off);
        sred[tid] = acc;
        if (cq == 0) sz2[rg] = z2;
        __syncthreads();

        if (rg == 0) {
            float4 t = sred[cq];
            #pragma unroll
            for (int g = 1; g < 8; ++g) {
                float4 v = sred[g * 32 + cq];
                t.x += v.x; t.y += v.y; t.z += v.z; t.w += v.w;
            }
            ((float4*)(g_zsum + ((size_t)b * NCHUNK + chunk) * C_))[cq] = t;
            if (cq == 0) {
                float tt = 0.f;
                #pragma unroll
                for (int g = 0; g < 8; ++g) tt += sz2[g];
                g_z2[(size_t)b * NCHUNK + chunk] = tt;
            }
        }
    }
    __syncthreads();

    // ---- MMA phase: warp grid 4(M) x 2(N); warp tile 32x64; k-steps of 16 ----
    const int warpM = wid & 3;
    const int warpN = wid >> 2;
    const int lq = lane >> 2;   // 0..7
    const int lr = lane & 3;    // 0..3

    float acc[2][8][4];
    #pragma unroll
    for (int mi = 0; mi < 2; ++mi)
        #pragma unroll
        for (int ni = 0; ni < 8; ++ni)
            #pragma unroll
            for (int j = 0; j < 4; ++j) acc[mi][ni][j] = 0.f;

    #pragma unroll
    for (int ks = 0; ks < 4; ++ks) {          // k0 = 16*ks; word base = 8*ks
        const int kw = 8 * ks + lr;
        uint32_t ah[2][4], al[2][4];
        #pragma unroll
        for (int mi = 0; mi < 2; ++mi) {
            const int r = warpM * 32 + mi * 16 + lq;
            const uint32_t* bh = sAh + r * PITCH_W + kw;
            const uint32_t* bl = sAl + r * PITCH_W + kw;
            ah[mi][0] = bh[0];
            ah[mi][1] = bh[8 * PITCH_W];
            ah[mi][2] = bh[4];
            ah[mi][3] = bh[8 * PITCH_W + 4];
            al[mi][0] = bl[0];
            al[mi][1] = bl[8 * PITCH_W];
            al[mi][2] = bl[4];
            al[mi][3] = bl[8 * PITCH_W + 4];
        }
        #pragma unroll
        for (int ni = 0; ni < 8; ++ni) {
            const int n = warpN * 64 + ni * 8 + lq;
            const uint32_t* bh = sBh + n * PITCH_W + kw;
            const uint32_t* bl = sBl + n * PITCH_W + kw;
            const uint32_t bh0 = bh[0], bh1 = bh[4];
            const uint32_t bl0 = bl[0], bl1 = bl[4];
            #pragma unroll
            for (int mi = 0; mi < 2; ++mi) {
                mma_bf16(acc[mi][ni], ah[mi], bh0, bh1);  // hi*hi
                mma_bf16(acc[mi][ni], ah[mi], bl0, bl1);  // hi*lo
                mma_bf16(acc[mi][ni], al[mi], bh0, bh1);  // lo*hi
            }
        }
    }

    // ---- epilogue ----
    #pragma unroll
    for (int mi = 0; mi < 2; ++mi) {
        const size_t row = m0 + warpM * 32 + mi * 16 + lq;
        #pragma unroll
        for (int ni = 0; ni < 8; ++ni) {
            const int col = warpN * 64 + ni * 8 + 2 * lr;
            *(float2*)(out + row * C_ + col) =
                make_float2(acc[mi][ni][0], acc[mi][ni][1]);
            *(float2*)(out + (row + 8) * C_ + col) =
                make_float2(acc[mi][ni][2], acc[mi][ni][3]);
        }
    }
}

// ---------------- Kernel 2: distance (parallelized) ----------------
__global__ __launch_bounds__(256)
void dist_kernel(const float* __restrict__ kk, float* __restrict__ dist) {
    const int b = blockIdx.x;
    const int tid = threadIdx.x;
    __shared__ float part[2][C_];
    __shared__ float zs[C_];
    __shared__ float z2s;

    {
        const int c    = tid & 127;
        const int half = tid >> 7;
        const float* base = g_zsum + ((size_t)b * NCHUNK + half * 16) * C_ + c;
        float a = 0.f;
        #pragma unroll
        for (int ch = 0; ch < 16; ++ch) a += base[(size_t)ch * C_];
        part[half][c] = a;
    }
    if (tid < 32) {
        float t = g_z2[(size_t)b * NCHUNK + tid];
        #pragma unroll
        for (int off = 16; off > 0; off >>= 1)
            t += __shfl_down_sync(0xffffffffu, t, off);
        if (tid == 0) z2s = t;
    }
    __syncthreads();
    if (tid < C_) zs[tid] = part[0][tid] + part[1][tid];
    __syncthreads();

    {
        const int p   = tid >> 2;
        const int sub = tid & 3;
        const float* kp = kk + (size_t)p * C_ + sub * 32;
        const float* zp = zs + sub * 32;
        float dot = 0.f, k2 = 0.f;
        #pragma unroll
        for (int c = 0; c < 32; ++c) {
            const float kv = kp[c];
            dot += zp[c] * kv;
            k2  += kv * kv;
        }
        dot += __shfl_xor_sync(0xffffffffu, dot, 1);
        k2  += __shfl_xor_sync(0xffffffffu, k2, 1);
        dot += __shfl_xor_sync(0xffffffffu, dot, 2);
        k2  += __shfl_xor_sync(0xffffffffu, k2, 2);
        if (sub == 0)
            dist[(size_t)b * P_ + p] = z2s - 2.f * dot + (float)HW_ * k2;
    }
}

// ---------------- launch ----------------
extern "C" void kernel_launch(void* const* d_in, const int* in_sizes, int n_in,
                              void* d_out, int out_size) {
    const float* z = (const float*)d_in[0];
    const float* s = (const float*)d_in[1];
    const float* k = (const float*)d_in[2];
    float* out  = (float*)d_out;
    float* dist = out + (size_t)in_sizes[0];

    static bool attr_set = false;
    if (!attr_set) {
        cudaFuncSetAttribute(fused_kernel,
                             cudaFuncAttributeMaxDynamicSharedMemorySize,
                             SMEM_WORDS * (int)sizeof(uint32_t));
        attr_set = true;
    }

    fused_kernel<<<(B_ * HW_) / TILE_M, 256, SMEM_WORDS * sizeof(uint32_t)>>>(
        z, s, k, out);
    dist_kernel<<<B_, 256>>>(k, dist);
}

// round 13
// speedup vs baseline: 1.5927x; 1.1973x over previous
#include <cuda_runtime.h>
#include <cstdint>

#define B_  64
#define HW_ 4096
#define C_  128      // N
#define P_  64       // K
#define NCHUNK 32
#define TILE_M 128

// smem tiles (bf16 hi/lo), pitch 72 bf16 (=36 words) for conflict-free frags
#define PITCH_W 36                       // words per row
#define A_TILE_W (128 * PITCH_W)
#define B_TILE_W (128 * PITCH_W)
#define SMEM_WORDS (2 * A_TILE_W + 2 * B_TILE_W)   // 73728 bytes

// ---------------- scratch ----------------
__device__ float g_zsum[(size_t)B_ * NCHUNK * C_];
__device__ float g_z2[(size_t)B_ * NCHUNK];

// ---------------- helpers ----------------
__device__ __forceinline__ uint32_t bf16x2_rn(float a, float b) {
    uint32_t r;
    asm("cvt.rn.bf16x2.f32 %0, %1, %2;" : "=r"(r) : "f"(b), "f"(a));
    return r;
}
__device__ __forceinline__ void split2(float a, float b, uint32_t& h, uint32_t& l) {
    h = bf16x2_rn(a, b);
    const float fh0 = __uint_as_float(h << 16);
    const float fh1 = __uint_as_float(h & 0xFFFF0000u);
    l = bf16x2_rn(a - fh0, b - fh1);
}

__device__ __forceinline__ void mma_bf16(float* d, const uint32_t* a,
                                         uint32_t b0, uint32_t b1) {
    asm volatile(
        "mma.sync.aligned.m16n8k16.row.col.f32.bf16.bf16.f32 "
        "{%0,%1,%2,%3}, {%4,%5,%6,%7}, {%8,%9}, {%0,%1,%2,%3};"
        : "+f"(d[0]), "+f"(d[1]), "+f"(d[2]), "+f"(d[3])
        : "r"(a[0]), "r"(a[1]), "r"(a[2]), "r"(a[3]), "r"(b0), "r"(b1));
}

// ---------------- fused kernel: z-reduce + 3xBF16 GEMM ----------------
__global__ __launch_bounds__(256, 2)
void fused_kernel(const float* __restrict__ z, const float* __restrict__ s,
                  const float* __restrict__ kk, float* __restrict__ out) {
    extern __shared__ uint32_t sm[];
    uint32_t* sAh = sm;                    // [128 m][36 w]  A hi
    uint32_t* sAl = sAh + A_TILE_W;        // A lo
    uint32_t* sBh = sAl + A_TILE_W;        // [128 n][36 w]  B hi
    uint32_t* sBl = sBh + B_TILE_W;        // B lo

    __shared__ float4 sred[256];
    __shared__ float  sz2[8];

    const int tid  = threadIdx.x;
    const int wid  = tid >> 5;
    const int lane = tid & 31;
    const int bx   = blockIdx.x;
    const size_t m0 = (size_t)bx * TILE_M;

    // ---- stage A (s tile): [m][k], k-contiguous ----
    #pragma unroll
    for (int i = 0; i < 8; ++i) {
        const int idx = tid + i * 256;          // 0..2047 float4
        const int r = idx >> 4, q = idx & 15;
        float4 v = ((const float4*)(s + (m0 + r) * P_))[q];
        uint32_t h0, l0, h1, l1;
        split2(v.x, v.y, h0, l0);
        split2(v.z, v.w, h1, l1);
        uint32_t* ph = sAh + r * PITCH_W + q * 2;
        uint32_t* pl = sAl + r * PITCH_W + q * 2;
        ph[0] = h0; ph[1] = h1;
        pl[0] = l0; pl[1] = l1;
    }
    // ---- stage B (k): kp = lane (conflict-free STS; k is L1/L2-hot) ----
    #pragma unroll
    for (int i = 0; i < 4; ++i) {
        const int idx = tid + i * 256;          // 0..1023
        const int kp = idx & 31;                // == lane; k rows 2kp, 2kp+1
        const int cq = idx >> 5;                // float4 along c (const/warp)
        float4 v0 = ((const float4*)(kk + (size_t)(2 * kp)     * C_))[cq];
        float4 v1 = ((const float4*)(kk + (size_t)(2 * kp + 1) * C_))[cq];
        const int n0 = cq * 4;
        uint32_t h, l;
        split2(v0.x, v1.x, h, l);
        sBh[(n0 + 0) * PITCH_W + kp] = h; sBl[(n0 + 0) * PITCH_W + kp] = l;
        split2(v0.y, v1.y, h, l);
        sBh[(n0 + 1) * PITCH_W + kp] = h; sBl[(n0 + 1) * PITCH_W + kp] = l;
        split2(v0.z, v1.z, h, l);
        sBh[(n0 + 2) * PITCH_W + kp] = h; sBl[(n0 + 2) * PITCH_W + kp] = l;
        split2(v0.w, v1.w, h, l);
        sBh[(n0 + 3) * PITCH_W + kp] = h; sBl[(n0 + 3) * PITCH_W + kp] = l;
    }

    // ---- z reduction phase ----
    {
        const int b     = bx >> 5;
        const int chunk = bx & 31;
        const float4* base =
            (const float4*)(z + ((size_t)b * HW_ + (size_t)chunk * 128) * C_);
        const int cq = tid & 31;
        const int rg = tid >> 5;

        float4 acc = make_float4(0.f, 0.f, 0.f, 0.f);
        float z2 = 0.f;
        #pragma unroll
        for (int j = 0; j < 16; ++j) {
            float4 v = base[(size_t)(rg + 8 * j) * (C_ / 4) + cq];
            acc.x += v.x; acc.y += v.y; acc.z += v.z; acc.w += v.w;
            z2 += v.x * v.x + v.y * v.y + v.z * v.z + v.w * v.w;
        }
        #pragma unroll
        for (int off = 16; off > 0; off >>= 1)
            z2 += __shfl_down_sync(0xffffffffu, z2, off);
        sred[tid] = acc;
        if (cq == 0) sz2[rg] = z2;
        __syncthreads();

        if (rg == 0) {
            float4 t = sred[cq];
            #pragma unroll
            for (int g = 1; g < 8; ++g) {
                float4 v = sred[g * 32 + cq];
                t.x += v.x; t.y += v.y; t.z += v.z; t.w += v.w;
            }
            ((float4*)(g_zsum + ((size_t)b * NCHUNK + chunk) * C_))[cq] = t;
            if (cq == 0) {
                float tt = 0.f;
                #pragma unroll
                for (int g = 0; g < 8; ++g) tt += sz2[g];
                g_z2[(size_t)b * NCHUNK + chunk] = tt;
            }
        }
    }
    __syncthreads();

    // ---- MMA phase: warp grid 4(M) x 2(N); warp tile 32x64; k-steps of 16 ----
    const int warpM = wid & 3;
    const int warpN = wid >> 2;
    const int lq = lane >> 2;   // 0..7
    const int lr = lane & 3;    // 0..3

    float acc[2][8][4];
    #pragma unroll
    for (int mi = 0; mi < 2; ++mi)
        #pragma unroll
        for (int ni = 0; ni < 8; ++ni)
            #pragma unroll
            for (int j = 0; j < 4; ++j) acc[mi][ni][j] = 0.f;

    #pragma unroll
    for (int ks = 0; ks < 4; ++ks) {
        const int kw = 8 * ks + lr;
        uint32_t ah[2][4], al[2][4];
        #pragma unroll
        for (int mi = 0; mi < 2; ++mi) {
            const int r = warpM * 32 + mi * 16 + lq;
            const uint32_t* bh = sAh + r * PITCH_W + kw;
            const uint32_t* bl = sAl + r * PITCH_W + kw;
            ah[mi][0] = bh[0];
            ah[mi][1] = bh[8 * PITCH_W];
            ah[mi][2] = bh[4];
            ah[mi][3] = bh[8 * PITCH_W + 4];
            al[mi][0] = bl[0];
            al[mi][1] = bl[8 * PITCH_W];
            al[mi][2] = bl[4];
            al[mi][3] = bl[8 * PITCH_W + 4];
        }
        #pragma unroll
        for (int ni = 0; ni < 8; ++ni) {
            const int n = warpN * 64 + ni * 8 + lq;
            const uint32_t* bh = sBh + n * PITCH_W + kw;
            const uint32_t* bl = sBl + n * PITCH_W + kw;
            const uint32_t bh0 = bh[0], bh1 = bh[4];
            const uint32_t bl0 = bl[0], bl1 = bl[4];
            #pragma unroll
            for (int mi = 0; mi < 2; ++mi) {
                mma_bf16(acc[mi][ni], ah[mi], bh0, bh1);  // hi*hi
                mma_bf16(acc[mi][ni], ah[mi], bl0, bl1);  // hi*lo
                mma_bf16(acc[mi][ni], al[mi], bh0, bh1);  // lo*hi
            }
        }
    }

    // ---- epilogue ----
    #pragma unroll
    for (int mi = 0; mi < 2; ++mi) {
        const size_t row = m0 + warpM * 32 + mi * 16 + lq;
        #pragma unroll
        for (int ni = 0; ni < 8; ++ni) {
            const int col = warpN * 64 + ni * 8 + 2 * lr;
            *(float2*)(out + row * C_ + col) =
                make_float2(acc[mi][ni][0], acc[mi][ni][1]);
            *(float2*)(out + (row + 8) * C_ + col) =
                make_float2(acc[mi][ni][2], acc[mi][ni][3]);
        }
    }
}

// ---------------- Kernel 2: distance ----------------
__global__ __launch_bounds__(256)
void dist_kernel(const float* __restrict__ kk, float* __restrict__ dist) {
    const int b = blockIdx.x;
    const int tid = threadIdx.x;
    __shared__ float part[2][C_];
    __shared__ float zs[C_];
    __shared__ float z2s;

    {
        const int c    = tid & 127;
        const int half = tid >> 7;
        const float* base = g_zsum + ((size_t)b * NCHUNK + half * 16) * C_ + c;
        float a = 0.f;
        #pragma unroll
        for (int ch = 0; ch < 16; ++ch) a += base[(size_t)ch * C_];
        part[half][c] = a;
    }
    if (tid < 32) {
        float t = g_z2[(size_t)b * NCHUNK + tid];
        #pragma unroll
        for (int off = 16; off > 0; off >>= 1)
            t += __shfl_down_sync(0xffffffffu, t, off);
        if (tid == 0) z2s = t;
    }
    __syncthreads();
    if (tid < C_) zs[tid] = part[0][tid] + part[1][tid];
    __syncthreads();

    {
        const int p   = tid >> 2;
        const int sub = tid & 3;
        const float* kp = kk + (size_t)p * C_ + sub * 32;
        const float* zp = zs + sub * 32;
        float dot = 0.f, k2 = 0.f;
        #pragma unroll
        for (int c = 0; c < 32; ++c) {
            const float kv = kp[c];
            dot += zp[c] * kv;
            k2  += kv * kv;
        }
        dot += __shfl_xor_sync(0xffffffffu, dot, 1);
        k2  += __shfl_xor_sync(0xffffffffu, k2, 1);
        dot += __shfl_xor_sync(0xffffffffu, dot, 2);
        k2  += __shfl_xor_sync(0xffffffffu, k2, 2);
        if (sub == 0)
            dist[(size_t)b * P_ + p] = z2s - 2.f * dot + (float)HW_ * k2;
    }
}

// ---------------- launch ----------------
extern "C" void kernel_launch(void* const* d_in, const int* in_sizes, int n_in,
                              void* d_out, int out_size) {
    const float* z = (const float*)d_in[0];
    const float* s = (const float*)d_in[1];
    const float* k = (const float*)d_in[2];
    float* out  = (float*)d_out;
    float* dist = out + (size_t)in_sizes[0];

    static bool attr_set = false;
    if (!attr_set) {
        cudaFuncSetAttribute(fused_kernel,
                             cudaFuncAttributeMaxDynamicSharedMemorySize,
                             SMEM_WORDS * (int)sizeof(uint32_t));
        attr_set = true;
    }

    fused_kernel<<<(B_ * HW_) / TILE_M, 256, SMEM_WORDS * sizeof(uint32_t)>>>(
        z, s, k, out);
    dist_kernel<<<B_, 256>>>(k, dist);
}